// round 16
// baseline (speedup 1.0000x reference)
#include <cuda_runtime.h>
#include <cuda_fp16.h>
#include <math.h>
#include <stdint.h>

// Problem constants
#define BB 4
#define LL 2048
#define DM 1024
#define DS 64
#define DI 2048
#define MROWS (BB*LL)        // 8192
#define N1 (2*DI)            // 4096
#define N2 (2*DS + DI)       // 2176
#define K3 192               // stacked-K for GEMM3 (hi*hi + hi*lo + lo*hi)
#define SPLITK4 4            // GEMM4 split-K factor

// ---------------- scratch (device globals; no allocations allowed) -------------
__device__ float g_xs  [(size_t)MROWS*DI];   // silu(xs) fp32 (scan)
__device__ float g_sres[(size_t)MROWS*DI];   // silu(res)
__device__ float g_Bsel[(size_t)MROWS*DS];
__device__ float g_Csel[(size_t)MROWS*DI];
__device__ float g_delta[(size_t)MROWS*DI];
__device__ float g_z   [(size_t)MROWS*DM];
__device__ float g_Aneg2[(size_t)DI*DS];     // -exp(A_log) * log2(e)

// fp16 operand buffers (weights transposed to [N][K])
__device__ __half g_xh   [(size_t)MROWS*DM];
__device__ __half g_Wit  [(size_t)N1*DM];
__device__ __half g_Wxt  [(size_t)N2*DI];
__device__ __half g_Wot  [(size_t)DM*DI];
__device__ __half g_Wdt3t[(size_t)DI*K3];    // [n][k]: k<64 hi, 64..127 lo, 128..191 hi
__device__ __half g_xsh  [(size_t)MROWS*DI];
__device__ __half g_draw3[(size_t)MROWS*K3]; // [hi | hi | lo] planes
__device__ __half g_yh   [(size_t)MROWS*DI];

__device__ __forceinline__ float ex2f(float x) {
    float r;
    asm("ex2.approx.ftz.f32 %0, %1;" : "=f"(r) : "f"(x));
    return r;
}
__device__ __forceinline__ void ldsm4(uint32_t& r0, uint32_t& r1, uint32_t& r2, uint32_t& r3,
                                      uint32_t addr) {
    asm volatile("ldmatrix.sync.aligned.m8n8.x4.shared.b16 {%0,%1,%2,%3}, [%4];"
                 : "=r"(r0), "=r"(r1), "=r"(r2), "=r"(r3) : "r"(addr));
}

// ---------------- prep kernels --------------------------------------------------
__global__ void aneg_kernel(const float* __restrict__ A_log) {
    int i = blockIdx.x * blockDim.x + threadIdx.x;
    if (i < DI*DS) g_Aneg2[i] = -__expf(A_log[i]) * 1.4426950408889634f;
}
__global__ void cvt_half_kernel(const float* __restrict__ in, __half* __restrict__ out, int n) {
    int i = blockIdx.x * blockDim.x + threadIdx.x;
    if (i < n) out[i] = __float2half(in[i]);
}
// W[K][N] -> Wt[N][K] fp16. block (32,8), grid (N/32, K/32)
__global__ void tcvt_kernel(const float* __restrict__ W, __half* __restrict__ Wt,
                            int K, int N) {
    __shared__ float t[32][33];
    int n0 = blockIdx.x * 32, k0 = blockIdx.y * 32;
#pragma unroll
    for (int i = 0; i < 4; ++i) {
        int k = k0 + threadIdx.y + i * 8;
        t[threadIdx.y + i * 8][threadIdx.x] = W[(size_t)k * N + n0 + threadIdx.x];
    }
    __syncthreads();
#pragma unroll
    for (int i = 0; i < 4; ++i) {
        int n = n0 + threadIdx.y + i * 8;
        Wt[(size_t)n * K + k0 + threadIdx.x] = __float2half(t[threadIdx.x][threadIdx.y + i * 8]);
    }
}
// Wdt[64][2048] -> Wdt3t[2048][192] fp16: planes [hi ; lo ; hi] along k
__global__ void wdt3t_kernel(const float* __restrict__ Wdt) {
    int i = blockIdx.x * blockDim.x + threadIdx.x;
    if (i < DS*DI) {
        int k = i / DI, n = i % DI;
        float v  = Wdt[i];
        __half hi = __float2half(v);
        __half lo = __float2half(v - __half2float(hi));
        g_Wdt3t[(size_t)n * K3 + k]        = hi;
        g_Wdt3t[(size_t)n * K3 + k + DS]   = lo;
        g_Wdt3t[(size_t)n * K3 + k + 2*DS] = hi;
    }
}

// =====================================================================
// FP16 tensor-core GEMM (m16n8k16, fp32 accum), ldmatrix + swizzle.
// CTA 128x128, 4 warps (64x64), BK=32, 4-stage cp.async, one barrier/kt,
// ldmatrix hoisted, paired 8B epilogue stores.
// Kstride = row stride of A/B (full K); K = this launch's K extent.
// blockIdx.z = K-slice (GEMM4 split-K; others launch z=1).
// EPI: 0 silu->(xs fp32 + xs fp16 | sres)
//      1 split(draw hi/hi/lo fp16 | Bsel | Csel)
//      2 softplus -> O0
//      3 split-K atomic accumulate into O0 (+bias+aux on slice 0)
// =====================================================================
#define BKT 32
#define ROWB 64                        // bytes per smem row (32 fp16)
#define TILE_BYTES (128*ROWB)          // 8192
#define STAGE_BYTES (2*TILE_BYTES)     // 16384
#define STG 4
#define SMEM_TC_BYTES (STG*STAGE_BYTES)   // 65536

template<int EPI>
__global__ __launch_bounds__(128)
void gemm_tc(const __half* __restrict__ A, const __half* __restrict__ B,
             const float* __restrict__ bias, const float* __restrict__ aux,
             float* __restrict__ O0, float* __restrict__ O1, float* __restrict__ O2,
             __half* __restrict__ OH,
             int M, int N, int K, int Kstride)
{
    extern __shared__ char smc[];
    const uint32_t smem_u = (uint32_t)__cvta_generic_to_shared(smc);
    const int tid  = threadIdx.x;
    const int lane = tid & 31;
    const int wid  = tid >> 5;
    const int wm   = wid & 1;     // warp row (2)
    const int wn   = wid >> 1;    // warp col (2)
    const int bx   = blockIdx.x, by = blockIdx.y;
    const int ksl  = blockIdx.z;

    const __half* Ag = A + (size_t)(by * 128) * Kstride + (size_t)ksl * K;
    const __half* Bg = B + (size_t)(bx * 128) * Kstride + (size_t)ksl * K;

    // cp.async mapping: thread t -> row (t>>2)+32i, chunk (t&3)
    const int crow = tid >> 2;
    const int cch  = tid & 3;

    auto issue = [&](int kt, int stage) {
        const int k0 = kt * BKT;
        const uint32_t As = smem_u + stage * STAGE_BYTES;
        const uint32_t Bs = As + TILE_BYTES;
#pragma unroll
        for (int i = 0; i < 4; ++i) {
            const int r = crow + i * 32;
            const int sc = cch ^ ((r >> 1) & 3);
            const uint32_t so = (uint32_t)(r * ROWB + sc * 16);
            asm volatile("cp.async.cg.shared.global [%0], [%1], 16;\n"
                         :: "r"(As + so), "l"(Ag + (size_t)r * Kstride + k0 + cch * 8));
            asm volatile("cp.async.cg.shared.global [%0], [%1], 16;\n"
                         :: "r"(Bs + so), "l"(Bg + (size_t)r * Kstride + k0 + cch * 8));
        }
    };

    const int KT = K / BKT;

    for (int s = 0; s < 3; ++s) {
        if (s < KT) issue(s, s);
        asm volatile("cp.async.commit_group;\n");
    }

    float acc[4][8][4];
#pragma unroll
    for (int i = 0; i < 4; ++i)
#pragma unroll
        for (int j = 0; j < 8; ++j)
#pragma unroll
            for (int q = 0; q < 4; ++q) acc[i][j][q] = 0.0f;

    // ldmatrix lane -> row / chunk-half decomposition
    const int arow_l  = wm * 64 + (lane & 7) + ((lane >> 3) & 1) * 8;   // + mf*16
    const int achalf  = lane >> 4;
    const int brow_l  = wn * 64 + (lane & 7) + (lane >> 4) * 8;         // + p*16
    const int bchalf  = (lane >> 3) & 1;

    uint32_t a_off[4]; int a_sw[4];
#pragma unroll
    for (int mf = 0; mf < 4; ++mf) {
        const int r = arow_l + mf * 16;
        a_off[mf] = (uint32_t)(r * ROWB);
        a_sw[mf]  = (r >> 1) & 3;
    }
    uint32_t b_off[4]; int b_sw[4];
#pragma unroll
    for (int p = 0; p < 4; ++p) {
        const int r = brow_l + p * 16;
        b_off[p] = (uint32_t)(r * ROWB);
        b_sw[p]  = (r >> 1) & 3;
    }

    for (int kt = 0; kt < KT; ++kt) {
        asm volatile("cp.async.wait_group 2;\n");
        __syncthreads();

        if (kt + 3 < KT) issue(kt + 3, (kt + 3) & 3);
        asm volatile("cp.async.commit_group;\n");

        const uint32_t As = smem_u + (kt & 3) * STAGE_BYTES;
        const uint32_t Bs = As + TILE_BYTES;

        uint32_t af[2][4][4], bf[2][8][2];
#pragma unroll
        for (int kk = 0; kk < 2; ++kk) {
#pragma unroll
            for (int mf = 0; mf < 4; ++mf) {
                const uint32_t addr = As + a_off[mf]
                    + (uint32_t)(((kk * 2 + achalf) ^ a_sw[mf]) << 4);
                ldsm4(af[kk][mf][0], af[kk][mf][1], af[kk][mf][2], af[kk][mf][3], addr);
            }
#pragma unroll
            for (int p = 0; p < 4; ++p) {
                const uint32_t addr = Bs + b_off[p]
                    + (uint32_t)(((kk * 2 + bchalf) ^ b_sw[p]) << 4);
                ldsm4(bf[kk][2*p][0], bf[kk][2*p][1], bf[kk][2*p+1][0], bf[kk][2*p+1][1], addr);
            }
        }
#pragma unroll
        for (int kk = 0; kk < 2; ++kk)
#pragma unroll
            for (int mf = 0; mf < 4; ++mf)
#pragma unroll
                for (int nf = 0; nf < 8; ++nf) {
                    asm volatile(
                        "mma.sync.aligned.m16n8k16.row.col.f32.f16.f16.f32 "
                        "{%0,%1,%2,%3}, {%4,%5,%6,%7}, {%8,%9}, {%0,%1,%2,%3};"
                        : "+f"(acc[mf][nf][0]), "+f"(acc[mf][nf][1]),
                          "+f"(acc[mf][nf][2]), "+f"(acc[mf][nf][3])
                        : "r"(af[kk][mf][0]), "r"(af[kk][mf][1]),
                          "r"(af[kk][mf][2]), "r"(af[kk][mf][3]),
                          "r"(bf[kk][nf][0]), "r"(bf[kk][nf][1]));
                }
        // no bottom __syncthreads — next top barrier orders stage reuse
    }

    // -------- epilogue (paired 8B stores; pairs never straddle splits) --------
#pragma unroll
    for (int mf = 0; mf < 4; ++mf) {
        const int r0 = by * 128 + wm * 64 + mf * 16 + (lane >> 2);
#pragma unroll
        for (int nf = 0; nf < 8; ++nf) {
            const int c0 = bx * 128 + wn * 64 + nf * 8 + 2 * (lane & 3);
            const float b0 = bias[c0], b1 = bias[c0 + 1];
#pragma unroll
            for (int half_ = 0; half_ < 2; ++half_) {
                const int m = r0 + half_ * 8;
                float v0 = acc[mf][nf][half_ * 2 + 0] + b0;
                float v1 = acc[mf][nf][half_ * 2 + 1] + b1;
                if (EPI == 0) {
                    float s0 = v0 / (1.0f + __expf(-v0));
                    float s1 = v1 / (1.0f + __expf(-v1));
                    if (c0 < DI) {
                        *(float2*)(O0 + (size_t)m * DI + c0) = make_float2(s0, s1);
                        *(__half2*)(OH + (size_t)m * DI + c0) = __floats2half2_rn(s0, s1);
                    } else {
                        *(float2*)(O1 + (size_t)m * DI + (c0 - DI)) = make_float2(s0, s1);
                    }
                } else if (EPI == 1) {
                    if (c0 < DS) {
                        __half h0 = __float2half(v0), h1 = __float2half(v1);
                        __half l0 = __float2half(v0 - __half2float(h0));
                        __half l1 = __float2half(v1 - __half2float(h1));
                        __half2 hh = __halves2half2(h0, h1);
                        *(__half2*)(OH + (size_t)m * K3 + c0)        = hh;
                        *(__half2*)(OH + (size_t)m * K3 + c0 + DS)   = hh;
                        *(__half2*)(OH + (size_t)m * K3 + c0 + 2*DS) = __halves2half2(l0, l1);
                    } else if (c0 < 2*DS) {
                        *(float2*)(O1 + (size_t)m * DS + (c0 - DS)) = make_float2(v0, v1);
                    } else {
                        *(float2*)(O2 + (size_t)m * DI + (c0 - 2*DS)) = make_float2(v0, v1);
                    }
                } else if (EPI == 2) {
                    float s0 = (v0 > 20.0f) ? v0 : log1pf(__expf(v0));
                    float s1 = (v1 > 20.0f) ? v1 : log1pf(__expf(v1));
                    *(float2*)(O0 + (size_t)m * N + c0) = make_float2(s0, s1);
                } else {
                    // split-K atomic accumulate; bias + residual only on slice 0
                    float p0 = acc[mf][nf][half_ * 2 + 0];
                    float p1 = acc[mf][nf][half_ * 2 + 1];
                    if (ksl == 0) {
                        float2 a2 = *(const float2*)(aux + (size_t)m * N + c0);
                        p0 += b0 + a2.x;
                        p1 += b1 + a2.y;
                    }
                    atomicAdd(O0 + (size_t)m * N + c0,     p0);
                    atomicAdd(O0 + (size_t)m * N + c0 + 1, p1);
                }
            }
        }
    }
}

// =====================================================================
// Selective scan v4: fine-grained CTAs for SM load balance.
// 1024 CTAs (DI/8 x BB), 64 threads = 2 warps x 4 channels x 8 lanes.
// 1024/148 = 6.92 -> ceil loss 1.2% (was 15.6% at 256 CTAs).
// Same recurrence/warp math as v3; y emitted fp16.
// =====================================================================
#define SCH 8                    // channels per CTA
#define SC_T 32
#define SC_NT (LL/SC_T)          // 64
#define SC_ARR (SC_T*SCH)        // 256 floats per array
#define SC_BF  (SC_T*72)         // 2304 floats (64 data + 8 pad per row)
#define SC_STAGE (4*SC_ARR + SC_BF)  // 3328 floats
#define SC_YOFF (2*SC_STAGE)         // 6656
#define SC_SMEM ((SC_YOFF + SC_ARR)*4)   // 27648 bytes

__global__ __launch_bounds__(64)
void scan_kernel(const float* __restrict__ delta, const float* __restrict__ Bsel,
                 const float* __restrict__ xs,    const float* __restrict__ Csel,
                 const float* __restrict__ sres,  const float* __restrict__ Dp,
                 __half* __restrict__ yh)
{
    extern __shared__ float sm[];
    const int tid  = threadIdx.x;
    const int lane = tid & 31;
    const int w    = tid >> 5;                 // warp 0..1
    const int b    = blockIdx.y;
    const int d0   = blockIdx.x * SCH;
    const int cl   = (w << 2) + (lane >> 3);   // local channel 0..7
    const int sl   = lane & 7;                 // state octet
    const int d    = d0 + cl;

    float A2[8], h[8];
#pragma unroll
    for (int j = 0; j < 8; ++j) {
        A2[j] = g_Aneg2[d * DS + sl * 8 + j];
        h[j] = 0.0f;
    }
    const float Dpd = __ldg(Dp + d);

    // loaders: arrays: row = tid>>1 (0..31), half = tid&1 (16B = 4 floats)
    const int lrow = tid >> 1;
    const int lch  = tid & 1;
    auto load_tile = [&](int tl, int s) {
        float* bs = sm + s * SC_STAGE;
        const size_t rbase = (size_t)b * LL + tl * SC_T + lrow;
        const uint32_t so = (uint32_t)__cvta_generic_to_shared(bs + lrow * SCH + lch * 4);
        const size_t go = rbase * DI + d0 + lch * 4;
        asm volatile("cp.async.cg.shared.global [%0], [%1], 16;\n" :: "r"(so),              "l"(delta + go));
        asm volatile("cp.async.cg.shared.global [%0], [%1], 16;\n" :: "r"(so + SC_ARR*4),   "l"(xs    + go));
        asm volatile("cp.async.cg.shared.global [%0], [%1], 16;\n" :: "r"(so + 2*SC_ARR*4), "l"(Csel  + go));
        asm volatile("cp.async.cg.shared.global [%0], [%1], 16;\n" :: "r"(so + 3*SC_ARR*4), "l"(sres  + go));
        // B: 32 rows x 64 floats; thread covers 8 chunks of its row-half
        const float* gB = Bsel + rbase * DS;
        const uint32_t sb = (uint32_t)__cvta_generic_to_shared(bs + 4*SC_ARR + lrow * 72);
#pragma unroll
        for (int i = 0; i < 8; ++i) {
            const int c = lch * 8 + i;
            asm volatile("cp.async.cg.shared.global [%0], [%1], 16;\n"
                         :: "r"(sb + c * 16), "l"(gB + c * 4));
        }
    };

    load_tile(0, 0);
    asm volatile("cp.async.commit_group;\n");

    float* ys = sm + SC_YOFF;

    for (int tl = 0; tl < SC_NT; ++tl) {
        if (tl + 1 < SC_NT) load_tile(tl + 1, (tl + 1) & 1);
        asm volatile("cp.async.commit_group;\n");
        asm volatile("cp.async.wait_group 1;\n");
        __syncthreads();

        const float* bs = sm + (tl & 1) * SC_STAGE;

#pragma unroll 4
        for (int tt = 0; tt < SC_T; ++tt) {
            const float dt = bs[tt * SCH + cl];
            const float xv = bs[SC_ARR   + tt * SCH + cl];
            const float cv = bs[2*SC_ARR + tt * SCH + cl];
            const float sr = bs[3*SC_ARR + tt * SCH + cl];
            const float4 B0 = *(const float4*)&bs[4*SC_ARR + tt * 72 + sl * 8];
            const float4 B1 = *(const float4*)&bs[4*SC_ARR + tt * 72 + sl * 8 + 4];
            const float Bv[8] = {B0.x, B0.y, B0.z, B0.w, B1.x, B1.y, B1.z, B1.w};

            const float u = dt * xv;
#pragma unroll
            for (int j = 0; j < 8; ++j) {
                const float e = ex2f(dt * A2[j]);
                h[j] = fmaf(e, h[j], Bv[j] * u);
            }

            float s = ((h[0]+h[1]) + (h[2]+h[3])) + ((h[4]+h[5]) + (h[6]+h[7]));
            s += __shfl_xor_sync(0xffffffffu, s, 4);
            s += __shfl_xor_sync(0xffffffffu, s, 2);
            s += __shfl_xor_sync(0xffffffffu, s, 1);

            if (sl == 0) ys[tt * SCH + cl] = (cv * s + xv * Dpd) * sr;
        }
        __syncthreads();

        {
            const float4 v = *(const float4*)&ys[lrow * SCH + lch * 4];
            __half2 o0 = __floats2half2_rn(v.x, v.y);
            __half2 o1 = __floats2half2_rn(v.z, v.w);
            __half2* dst = (__half2*)(yh + ((size_t)b * LL + tl * SC_T + lrow) * DI + d0 + lch * 4);
            dst[0] = o0;
            dst[1] = o1;
        }
    }
}

// ---------------- layernorm ----------------------------------------------------
__device__ __forceinline__ float block_sum256(float v, float* sh) {
    __syncthreads();
#pragma unroll
    for (int o = 16; o; o >>= 1) v += __shfl_xor_sync(0xffffffffu, v, o);
    const int lane = threadIdx.x & 31, wid = threadIdx.x >> 5;
    if (lane == 0) sh[wid] = v;
    __syncthreads();
    if (threadIdx.x < 32) {
        float t = (lane < 8) ? sh[lane] : 0.0f;
#pragma unroll
        for (int o = 4; o; o >>= 1) t += __shfl_xor_sync(0xffffffffu, t, o);
        if (lane == 0) sh[8] = t;
    }
    __syncthreads();
    return sh[8];
}

__global__ __launch_bounds__(256)
void ln_kernel(const float* __restrict__ z, const float* __restrict__ gamma,
               const float* __restrict__ beta, float* __restrict__ out)
{
    __shared__ float sh[16];
    const int row = blockIdx.x;
    const float4 v = ((const float4*)(z + (size_t)row * DM))[threadIdx.x];

    float s  = (v.x + v.y) + (v.z + v.w);
    float S  = block_sum256(s, sh);
    float mu = S * (1.0f / DM);

    float dx = v.x - mu, dy = v.y - mu, dz = v.z - mu, dw = v.w - mu;
    float q  = (dx*dx + dy*dy) + (dz*dz + dw*dw);
    float Q  = block_sum256(q, sh);
    float inv = rsqrtf(Q * (1.0f / DM) + 1e-5f);

    const float4 g = ((const float4*)gamma)[threadIdx.x];
    const float4 bb = ((const float4*)beta)[threadIdx.x];
    float4 o;
    o.x = dx * inv * g.x + bb.x;
    o.y = dy * inv * g.y + bb.y;
    o.z = dz * inv * g.z + bb.z;
    o.w = dw * inv * g.w + bb.w;
    ((float4*)(out + (size_t)row * DM))[threadIdx.x] = o;
}

// ---------------- launch --------------------------------------------------------
extern "C" void kernel_launch(void* const* d_in, const int* in_sizes, int n_in,
                              void* d_out, int out_size)
{
    const float* x     = (const float*)d_in[0];
    const float* Wi    = (const float*)d_in[1];
    const float* bi    = (const float*)d_in[2];
    const float* Wx    = (const float*)d_in[3];
    const float* bx    = (const float*)d_in[4];
    const float* Wdt   = (const float*)d_in[5];
    const float* bdt   = (const float*)d_in[6];
    const float* A_log = (const float*)d_in[7];
    const float* Dp    = (const float*)d_in[8];
    const float* Wo    = (const float*)d_in[9];
    const float* bo    = (const float*)d_in[10];
    const float* gamma = (const float*)d_in[11];
    const float* beta  = (const float*)d_in[12];
    float* out = (float*)d_out;

    float *xs, *sres, *Bsel, *Csel, *delta, *z;
    __half *xh, *Wit, *Wxt, *Wot, *Wdt3t, *xsh, *draw3, *yh;
    cudaGetSymbolAddress((void**)&xs,    g_xs);
    cudaGetSymbolAddress((void**)&sres,  g_sres);
    cudaGetSymbolAddress((void**)&Bsel,  g_Bsel);
    cudaGetSymbolAddress((void**)&Csel,  g_Csel);
    cudaGetSymbolAddress((void**)&delta, g_delta);
    cudaGetSymbolAddress((void**)&z,     g_z);
    cudaGetSymbolAddress((void**)&xh,    g_xh);
    cudaGetSymbolAddress((void**)&Wit,   g_Wit);
    cudaGetSymbolAddress((void**)&Wxt,   g_Wxt);
    cudaGetSymbolAddress((void**)&Wot,   g_Wot);
    cudaGetSymbolAddress((void**)&Wdt3t, g_Wdt3t);
    cudaGetSymbolAddress((void**)&xsh,   g_xsh);
    cudaGetSymbolAddress((void**)&draw3, g_draw3);
    cudaGetSymbolAddress((void**)&yh,    g_yh);

    static bool attr_done = false;
    if (!attr_done) {
        cudaFuncSetAttribute(gemm_tc<0>, cudaFuncAttributeMaxDynamicSharedMemorySize, SMEM_TC_BYTES);
        cudaFuncSetAttribute(gemm_tc<1>, cudaFuncAttributeMaxDynamicSharedMemorySize, SMEM_TC_BYTES);
        cudaFuncSetAttribute(gemm_tc<2>, cudaFuncAttributeMaxDynamicSharedMemorySize, SMEM_TC_BYTES);
        cudaFuncSetAttribute(gemm_tc<3>, cudaFuncAttributeMaxDynamicSharedMemorySize, SMEM_TC_BYTES);
        cudaFuncSetAttribute(scan_kernel, cudaFuncAttributeMaxDynamicSharedMemorySize, SC_SMEM);
        attr_done = true;
    }

    // launches 1..3 (keeps gemm_tc<0> as 4th launch for ncu comparability)
    aneg_kernel<<<(DI*DS + 255)/256, 256>>>(A_log);
    cvt_half_kernel<<<(MROWS*DM + 255)/256, 256>>>(x, xh, MROWS*DM);
    tcvt_kernel<<<dim3(N1/32, DM/32), dim3(32, 8)>>>(Wi, Wit, DM, N1);

    // GEMM1 (4th launch): xh @ Wit^T + bi -> silu -> xs fp32 + xs fp16 | sres
    gemm_tc<0><<<dim3(N1/128, MROWS/128), 128, SMEM_TC_BYTES>>>(
        xh, Wit, bi, nullptr, xs, sres, nullptr, xsh, MROWS, N1, DM, DM);

    wdt3t_kernel<<<(DS*DI + 255)/256, 256>>>(Wdt);
    tcvt_kernel<<<dim3(N2/32, DI/32), dim3(32, 8)>>>(Wx, Wxt, DI, N2);
    tcvt_kernel<<<dim3(DM/32, DI/32), dim3(32, 8)>>>(Wo, Wot, DI, DM);

    // GEMM2: xsh @ Wxt^T + bx -> draw3(hi/hi/lo fp16) | Bsel | Csel
    gemm_tc<1><<<dim3(N2/128, MROWS/128), 128, SMEM_TC_BYTES>>>(
        xsh, Wxt, bx, nullptr, nullptr, Bsel, Csel, draw3, MROWS, N2, DI, DI);

    // GEMM3 (stacked-K fp16x2): draw3 @ Wdt3t^T + bdt -> softplus -> delta
    gemm_tc<2><<<dim3(DI/128, MROWS/128), 128, SMEM_TC_BYTES>>>(
        draw3, Wdt3t, bdt, nullptr, delta, nullptr, nullptr, nullptr, MROWS, DI, K3, K3);

    // selective scan v4 (fine-grained; emits fp16 y)
    scan_kernel<<<dim3(DI/SCH, BB), 64, SC_SMEM>>>(delta, Bsel, xs, Csel, sres, Dp, yh);

    // GEMM4: split-K=4 atomic accumulate: z = yh @ Wot^T + bo + x
    cudaMemsetAsync(z, 0, (size_t)MROWS * DM * sizeof(float));
    gemm_tc<3><<<dim3(DM/128, MROWS/128, SPLITK4), 128, SMEM_TC_BYTES>>>(
        yh, Wot, bo, x, z, nullptr, nullptr, nullptr, MROWS, DM, DI/SPLITK4, DI);

    // layernorm -> out
    ln_kernel<<<MROWS, 256>>>(z, gamma, beta, out);
}

// round 17
// speedup vs baseline: 1.1143x; 1.1143x over previous
#include <cuda_runtime.h>
#include <cuda_fp16.h>
#include <math.h>
#include <stdint.h>

// Problem constants
#define BB 4
#define LL 2048
#define DM 1024
#define DS 64
#define DI 2048
#define MROWS (BB*LL)        // 8192
#define N1 (2*DI)            // 4096
#define N2 (2*DS + DI)       // 2176
#define K3 192               // stacked-K for GEMM3 (hi*hi + hi*lo + lo*hi)

// ---------------- scratch (device globals; no allocations allowed) -------------
__device__ float g_xs  [(size_t)MROWS*DI];   // silu(xs) fp32 (scan)
__device__ float g_sres[(size_t)MROWS*DI];   // silu(res)
__device__ float g_Bsel[(size_t)MROWS*DS];
__device__ float g_Csel[(size_t)MROWS*DI];
__device__ float g_delta[(size_t)MROWS*DI];  // delta; reused as z2 after the scan
__device__ float g_z   [(size_t)MROWS*DM];
__device__ float g_Aneg2[(size_t)DI*DS];     // -exp(A_log) * log2(e)

// fp16 operand buffers (weights transposed to [N][K])
__device__ __half g_xh   [(size_t)MROWS*DM];
__device__ __half g_Wit  [(size_t)N1*DM];
__device__ __half g_Wxt  [(size_t)N2*DI];
__device__ __half g_Wot  [(size_t)DM*DI];
__device__ __half g_Wdt3t[(size_t)DI*K3];
__device__ __half g_xsh  [(size_t)MROWS*DI];
__device__ __half g_draw3[(size_t)MROWS*K3];
__device__ __half g_yh   [(size_t)MROWS*DI];

__device__ __forceinline__ float ex2f(float x) {
    float r;
    asm("ex2.approx.ftz.f32 %0, %1;" : "=f"(r) : "f"(x));
    return r;
}
__device__ __forceinline__ void ldsm4(uint32_t& r0, uint32_t& r1, uint32_t& r2, uint32_t& r3,
                                      uint32_t addr) {
    asm volatile("ldmatrix.sync.aligned.m8n8.x4.shared.b16 {%0,%1,%2,%3}, [%4];"
                 : "=r"(r0), "=r"(r1), "=r"(r2), "=r"(r3) : "r"(addr));
}

// ---------------- prep kernels --------------------------------------------------
__global__ void aneg_kernel(const float* __restrict__ A_log) {
    int i = blockIdx.x * blockDim.x + threadIdx.x;
    if (i < DI*DS) g_Aneg2[i] = -__expf(A_log[i]) * 1.4426950408889634f;
}
__global__ void cvt_half_kernel(const float* __restrict__ in, __half* __restrict__ out, int n) {
    int i = blockIdx.x * blockDim.x + threadIdx.x;
    if (i < n) out[i] = __float2half(in[i]);
}
__global__ void tcvt_kernel(const float* __restrict__ W, __half* __restrict__ Wt,
                            int K, int N) {
    __shared__ float t[32][33];
    int n0 = blockIdx.x * 32, k0 = blockIdx.y * 32;
#pragma unroll
    for (int i = 0; i < 4; ++i) {
        int k = k0 + threadIdx.y + i * 8;
        t[threadIdx.y + i * 8][threadIdx.x] = W[(size_t)k * N + n0 + threadIdx.x];
    }
    __syncthreads();
#pragma unroll
    for (int i = 0; i < 4; ++i) {
        int n = n0 + threadIdx.y + i * 8;
        Wt[(size_t)n * K + k0 + threadIdx.x] = __float2half(t[threadIdx.x][threadIdx.y + i * 8]);
    }
}
__global__ void wdt3t_kernel(const float* __restrict__ Wdt) {
    int i = blockIdx.x * blockDim.x + threadIdx.x;
    if (i < DS*DI) {
        int k = i / DI, n = i % DI;
        float v  = Wdt[i];
        __half hi = __float2half(v);
        __half lo = __float2half(v - __half2float(hi));
        g_Wdt3t[(size_t)n * K3 + k]        = hi;
        g_Wdt3t[(size_t)n * K3 + k + DS]   = lo;
        g_Wdt3t[(size_t)n * K3 + k + 2*DS] = hi;
    }
}

// =====================================================================
// FP16 tensor-core GEMM (m16n8k16, fp32 accum), ldmatrix + swizzle.
// CTA 128x128, 4 warps (64x64), BK=32, 4-stage cp.async, one barrier/kt,
// ldmatrix hoisted, paired 8B epilogue stores. blockIdx.z = K-slice.
// EPI: 0 silu->(xs fp32 + xs fp16 | sres)
//      1 split(draw hi/hi/lo fp16 | Bsel | Csel)
//      2 softplus -> O0
//      3 split-K=2: slice0 -> O0 (+bias+aux), slice1 -> O1 (raw partial)
// =====================================================================
#define BKT 32
#define ROWB 64
#define TILE_BYTES (128*ROWB)
#define STAGE_BYTES (2*TILE_BYTES)
#define STG 4
#define SMEM_TC_BYTES (STG*STAGE_BYTES)

template<int EPI>
__global__ __launch_bounds__(128)
void gemm_tc(const __half* __restrict__ A, const __half* __restrict__ B,
             const float* __restrict__ bias, const float* __restrict__ aux,
             float* __restrict__ O0, float* __restrict__ O1, float* __restrict__ O2,
             __half* __restrict__ OH,
             int M, int N, int K, int Kstride)
{
    extern __shared__ char smc[];
    const uint32_t smem_u = (uint32_t)__cvta_generic_to_shared(smc);
    const int tid  = threadIdx.x;
    const int lane = tid & 31;
    const int wid  = tid >> 5;
    const int wm   = wid & 1;
    const int wn   = wid >> 1;
    const int bx   = blockIdx.x, by = blockIdx.y;
    const int ksl  = blockIdx.z;

    const __half* Ag = A + (size_t)(by * 128) * Kstride + (size_t)ksl * K;
    const __half* Bg = B + (size_t)(bx * 128) * Kstride + (size_t)ksl * K;

    const int crow = tid >> 2;
    const int cch  = tid & 3;

    auto issue = [&](int kt, int stage) {
        const int k0 = kt * BKT;
        const uint32_t As = smem_u + stage * STAGE_BYTES;
        const uint32_t Bs = As + TILE_BYTES;
#pragma unroll
        for (int i = 0; i < 4; ++i) {
            const int r = crow + i * 32;
            const int sc = cch ^ ((r >> 1) & 3);
            const uint32_t so = (uint32_t)(r * ROWB + sc * 16);
            asm volatile("cp.async.cg.shared.global [%0], [%1], 16;\n"
                         :: "r"(As + so), "l"(Ag + (size_t)r * Kstride + k0 + cch * 8));
            asm volatile("cp.async.cg.shared.global [%0], [%1], 16;\n"
                         :: "r"(Bs + so), "l"(Bg + (size_t)r * Kstride + k0 + cch * 8));
        }
    };

    const int KT = K / BKT;

    for (int s = 0; s < 3; ++s) {
        if (s < KT) issue(s, s);
        asm volatile("cp.async.commit_group;\n");
    }

    float acc[4][8][4];
#pragma unroll
    for (int i = 0; i < 4; ++i)
#pragma unroll
        for (int j = 0; j < 8; ++j)
#pragma unroll
            for (int q = 0; q < 4; ++q) acc[i][j][q] = 0.0f;

    const int arow_l  = wm * 64 + (lane & 7) + ((lane >> 3) & 1) * 8;
    const int achalf  = lane >> 4;
    const int brow_l  = wn * 64 + (lane & 7) + (lane >> 4) * 8;
    const int bchalf  = (lane >> 3) & 1;

    uint32_t a_off[4]; int a_sw[4];
#pragma unroll
    for (int mf = 0; mf < 4; ++mf) {
        const int r = arow_l + mf * 16;
        a_off[mf] = (uint32_t)(r * ROWB);
        a_sw[mf]  = (r >> 1) & 3;
    }
    uint32_t b_off[4]; int b_sw[4];
#pragma unroll
    for (int p = 0; p < 4; ++p) {
        const int r = brow_l + p * 16;
        b_off[p] = (uint32_t)(r * ROWB);
        b_sw[p]  = (r >> 1) & 3;
    }

    for (int kt = 0; kt < KT; ++kt) {
        asm volatile("cp.async.wait_group 2;\n");
        __syncthreads();

        if (kt + 3 < KT) issue(kt + 3, (kt + 3) & 3);
        asm volatile("cp.async.commit_group;\n");

        const uint32_t As = smem_u + (kt & 3) * STAGE_BYTES;
        const uint32_t Bs = As + TILE_BYTES;

        uint32_t af[2][4][4], bf[2][8][2];
#pragma unroll
        for (int kk = 0; kk < 2; ++kk) {
#pragma unroll
            for (int mf = 0; mf < 4; ++mf) {
                const uint32_t addr = As + a_off[mf]
                    + (uint32_t)(((kk * 2 + achalf) ^ a_sw[mf]) << 4);
                ldsm4(af[kk][mf][0], af[kk][mf][1], af[kk][mf][2], af[kk][mf][3], addr);
            }
#pragma unroll
            for (int p = 0; p < 4; ++p) {
                const uint32_t addr = Bs + b_off[p]
                    + (uint32_t)(((kk * 2 + bchalf) ^ b_sw[p]) << 4);
                ldsm4(bf[kk][2*p][0], bf[kk][2*p][1], bf[kk][2*p+1][0], bf[kk][2*p+1][1], addr);
            }
        }
#pragma unroll
        for (int kk = 0; kk < 2; ++kk)
#pragma unroll
            for (int mf = 0; mf < 4; ++mf)
#pragma unroll
                for (int nf = 0; nf < 8; ++nf) {
                    asm volatile(
                        "mma.sync.aligned.m16n8k16.row.col.f32.f16.f16.f32 "
                        "{%0,%1,%2,%3}, {%4,%5,%6,%7}, {%8,%9}, {%0,%1,%2,%3};"
                        : "+f"(acc[mf][nf][0]), "+f"(acc[mf][nf][1]),
                          "+f"(acc[mf][nf][2]), "+f"(acc[mf][nf][3])
                        : "r"(af[kk][mf][0]), "r"(af[kk][mf][1]),
                          "r"(af[kk][mf][2]), "r"(af[kk][mf][3]),
                          "r"(bf[kk][nf][0]), "r"(bf[kk][nf][1]));
                }
    }

    // -------- epilogue --------
#pragma unroll
    for (int mf = 0; mf < 4; ++mf) {
        const int r0 = by * 128 + wm * 64 + mf * 16 + (lane >> 2);
#pragma unroll
        for (int nf = 0; nf < 8; ++nf) {
            const int c0 = bx * 128 + wn * 64 + nf * 8 + 2 * (lane & 3);
            const float b0 = bias[c0], b1 = bias[c0 + 1];
#pragma unroll
            for (int half_ = 0; half_ < 2; ++half_) {
                const int m = r0 + half_ * 8;
                float v0 = acc[mf][nf][half_ * 2 + 0] + b0;
                float v1 = acc[mf][nf][half_ * 2 + 1] + b1;
                if (EPI == 0) {
                    float s0 = v0 / (1.0f + __expf(-v0));
                    float s1 = v1 / (1.0f + __expf(-v1));
                    if (c0 < DI) {
                        *(float2*)(O0 + (size_t)m * DI + c0) = make_float2(s0, s1);
                        *(__half2*)(OH + (size_t)m * DI + c0) = __floats2half2_rn(s0, s1);
                    } else {
                        *(float2*)(O1 + (size_t)m * DI + (c0 - DI)) = make_float2(s0, s1);
                    }
                } else if (EPI == 1) {
                    if (c0 < DS) {
                        __half h0 = __float2half(v0), h1 = __float2half(v1);
                        __half l0 = __float2half(v0 - __half2float(h0));
                        __half l1 = __float2half(v1 - __half2float(h1));
                        __half2 hh = __halves2half2(h0, h1);
                        *(__half2*)(OH + (size_t)m * K3 + c0)        = hh;
                        *(__half2*)(OH + (size_t)m * K3 + c0 + DS)   = hh;
                        *(__half2*)(OH + (size_t)m * K3 + c0 + 2*DS) = __halves2half2(l0, l1);
                    } else if (c0 < 2*DS) {
                        *(float2*)(O1 + (size_t)m * DS + (c0 - DS)) = make_float2(v0, v1);
                    } else {
                        *(float2*)(O2 + (size_t)m * DI + (c0 - 2*DS)) = make_float2(v0, v1);
                    }
                } else if (EPI == 2) {
                    float s0 = (v0 > 20.0f) ? v0 : log1pf(__expf(v0));
                    float s1 = (v1 > 20.0f) ? v1 : log1pf(__expf(v1));
                    *(float2*)(O0 + (size_t)m * N + c0) = make_float2(s0, s1);
                } else {
                    float p0 = acc[mf][nf][half_ * 2 + 0];
                    float p1 = acc[mf][nf][half_ * 2 + 1];
                    if (ksl == 0) {
                        float2 a2 = *(const float2*)(aux + (size_t)m * N + c0);
                        *(float2*)(O0 + (size_t)m * N + c0) =
                            make_float2(p0 + b0 + a2.x, p1 + b1 + a2.y);
                    } else {
                        *(float2*)(O1 + (size_t)m * N + c0) = make_float2(p0, p1);
                    }
                }
            }
        }
    }
}

// =====================================================================
// Selective scan v3 (round-7/15 winner; y emitted fp16)
// =====================================================================
#define SC_T 32
#define SC_NT (LL/SC_T)
#define SC_ARR 1024
#define SC_BF  (32*72)
#define SC_STAGE (4*SC_ARR + SC_BF)
#define SC_YOFF (2*SC_STAGE)
#define SC_SMEM ((SC_YOFF + SC_ARR)*4)

__global__ __launch_bounds__(256)
void scan_kernel(const float* __restrict__ delta, const float* __restrict__ Bsel,
                 const float* __restrict__ xs,    const float* __restrict__ Csel,
                 const float* __restrict__ sres,  const float* __restrict__ Dp,
                 __half* __restrict__ yh)
{
    extern __shared__ float sm[];
    const int tid  = threadIdx.x;
    const int lane = tid & 31;
    const int w    = tid >> 5;
    const int b    = blockIdx.y;
    const int d0   = blockIdx.x * 32;
    const int cl   = (w << 2) + (lane >> 3);
    const int sl   = lane & 7;
    const int d    = d0 + cl;

    float A2[8], h[8];
#pragma unroll
    for (int j = 0; j < 8; ++j) {
        A2[j] = g_Aneg2[d * DS + sl * 8 + j];
        h[j] = 0.0f;
    }
    const float Dpd = __ldg(Dp + d);

    const int lrow = tid >> 3;
    const int lch  = tid & 7;
    auto load_tile = [&](int tl, int s) {
        float* bs = sm + s * SC_STAGE;
        const size_t rbase = (size_t)b * LL + tl * SC_T + lrow;
        const uint32_t so = (uint32_t)__cvta_generic_to_shared(bs + lrow * 32 + lch * 4);
        const size_t go = rbase * DI + d0 + lch * 4;
        asm volatile("cp.async.cg.shared.global [%0], [%1], 16;\n" :: "r"(so),              "l"(delta + go));
        asm volatile("cp.async.cg.shared.global [%0], [%1], 16;\n" :: "r"(so + SC_ARR*4),   "l"(xs    + go));
        asm volatile("cp.async.cg.shared.global [%0], [%1], 16;\n" :: "r"(so + 2*SC_ARR*4), "l"(Csel  + go));
        asm volatile("cp.async.cg.shared.global [%0], [%1], 16;\n" :: "r"(so + 3*SC_ARR*4), "l"(sres  + go));
        const float* gB = Bsel + rbase * DS;
        const uint32_t sb = (uint32_t)__cvta_generic_to_shared(bs + 4*SC_ARR + lrow * 72);
        asm volatile("cp.async.cg.shared.global [%0], [%1], 16;\n" :: "r"(sb + lch*16),        "l"(gB + lch*4));
        asm volatile("cp.async.cg.shared.global [%0], [%1], 16;\n" :: "r"(sb + (lch+8)*16),    "l"(gB + (lch+8)*4));
    };

    load_tile(0, 0);
    asm volatile("cp.async.commit_group;\n");

    float* ys = sm + SC_YOFF;

    for (int tl = 0; tl < SC_NT; ++tl) {
        if (tl + 1 < SC_NT) load_tile(tl + 1, (tl + 1) & 1);
        asm volatile("cp.async.commit_group;\n");
        asm volatile("cp.async.wait_group 1;\n");
        __syncthreads();

        const float* bs = sm + (tl & 1) * SC_STAGE;

#pragma unroll 4
        for (int tt = 0; tt < SC_T; ++tt) {
            const float dt = bs[tt * 32 + cl];
            const float xv = bs[SC_ARR   + tt * 32 + cl];
            const float cv = bs[2*SC_ARR + tt * 32 + cl];
            const float sr = bs[3*SC_ARR + tt * 32 + cl];
            const float4 B0 = *(const float4*)&bs[4*SC_ARR + tt * 72 + sl * 8];
            const float4 B1 = *(const float4*)&bs[4*SC_ARR + tt * 72 + sl * 8 + 4];
            const float Bv[8] = {B0.x, B0.y, B0.z, B0.w, B1.x, B1.y, B1.z, B1.w};

            const float u = dt * xv;
#pragma unroll
            for (int j = 0; j < 8; ++j) {
                const float e = ex2f(dt * A2[j]);
                h[j] = fmaf(e, h[j], Bv[j] * u);
            }

            float s = ((h[0]+h[1]) + (h[2]+h[3])) + ((h[4]+h[5]) + (h[6]+h[7]));
            s += __shfl_xor_sync(0xffffffffu, s, 4);
            s += __shfl_xor_sync(0xffffffffu, s, 2);
            s += __shfl_xor_sync(0xffffffffu, s, 1);

            if (sl == 0) ys[tt * 32 + cl] = (cv * s + xv * Dpd) * sr;
        }
        __syncthreads();

        {
            const float4 v = *(const float4*)&ys[lrow * 32 + lch * 4];
            __half2 o0 = __floats2half2_rn(v.x, v.y);
            __half2 o1 = __floats2half2_rn(v.z, v.w);
            __half2* dst = (__half2*)(yh + ((size_t)b * LL + tl * SC_T + lrow) * DI + d0 + lch * 4);
            dst[0] = o0;
            dst[1] = o1;
        }
    }
}

// ---------------- layernorm (sums the two split-K z buffers) -------------------
__device__ __forceinline__ float block_sum256(float v, float* sh) {
    __syncthreads();
#pragma unroll
    for (int o = 16; o; o >>= 1) v += __shfl_xor_sync(0xffffffffu, v, o);
    const int lane = threadIdx.x & 31, wid = threadIdx.x >> 5;
    if (lane == 0) sh[wid] = v;
    __syncthreads();
    if (threadIdx.x < 32) {
        float t = (lane < 8) ? sh[lane] : 0.0f;
#pragma unroll
        for (int o = 4; o; o >>= 1) t += __shfl_xor_sync(0xffffffffu, t, o);
        if (lane == 0) sh[8] = t;
    }
    __syncthreads();
    return sh[8];
}

__global__ __launch_bounds__(256)
void ln_kernel(const float* __restrict__ z, const float* __restrict__ z2,
               const float* __restrict__ gamma,
               const float* __restrict__ beta, float* __restrict__ out)
{
    __shared__ float sh[16];
    const int row = blockIdx.x;
    float4 v  = ((const float4*)(z  + (size_t)row * DM))[threadIdx.x];
    const float4 v2 = ((const float4*)(z2 + (size_t)row * DM))[threadIdx.x];
    v.x += v2.x; v.y += v2.y; v.z += v2.z; v.w += v2.w;

    float s  = (v.x + v.y) + (v.z + v.w);
    float S  = block_sum256(s, sh);
    float mu = S * (1.0f / DM);

    float dx = v.x - mu, dy = v.y - mu, dz = v.z - mu, dw = v.w - mu;
    float q  = (dx*dx + dy*dy) + (dz*dz + dw*dw);
    float Q  = block_sum256(q, sh);
    float inv = rsqrtf(Q * (1.0f / DM) + 1e-5f);

    const float4 g = ((const float4*)gamma)[threadIdx.x];
    const float4 bb = ((const float4*)beta)[threadIdx.x];
    float4 o;
    o.x = dx * inv * g.x + bb.x;
    o.y = dy * inv * g.y + bb.y;
    o.z = dz * inv * g.z + bb.z;
    o.w = dw * inv * g.w + bb.w;
    ((float4*)(out + (size_t)row * DM))[threadIdx.x] = o;
}

// ---------------- launch --------------------------------------------------------
extern "C" void kernel_launch(void* const* d_in, const int* in_sizes, int n_in,
                              void* d_out, int out_size)
{
    const float* x     = (const float*)d_in[0];
    const float* Wi    = (const float*)d_in[1];
    const float* bi    = (const float*)d_in[2];
    const float* Wx    = (const float*)d_in[3];
    const float* bx    = (const float*)d_in[4];
    const float* Wdt   = (const float*)d_in[5];
    const float* bdt   = (const float*)d_in[6];
    const float* A_log = (const float*)d_in[7];
    const float* Dp    = (const float*)d_in[8];
    const float* Wo    = (const float*)d_in[9];
    const float* bo    = (const float*)d_in[10];
    const float* gamma = (const float*)d_in[11];
    const float* beta  = (const float*)d_in[12];
    float* out = (float*)d_out;

    float *xs, *sres, *Bsel, *Csel, *delta, *z;
    __half *xh, *Wit, *Wxt, *Wot, *Wdt3t, *xsh, *draw3, *yh;
    cudaGetSymbolAddress((void**)&xs,    g_xs);
    cudaGetSymbolAddress((void**)&sres,  g_sres);
    cudaGetSymbolAddress((void**)&Bsel,  g_Bsel);
    cudaGetSymbolAddress((void**)&Csel,  g_Csel);
    cudaGetSymbolAddress((void**)&delta, g_delta);
    cudaGetSymbolAddress((void**)&z,     g_z);
    cudaGetSymbolAddress((void**)&xh,    g_xh);
    cudaGetSymbolAddress((void**)&Wit,   g_Wit);
    cudaGetSymbolAddress((void**)&Wxt,   g_Wxt);
    cudaGetSymbolAddress((void**)&Wot,   g_Wot);
    cudaGetSymbolAddress((void**)&Wdt3t, g_Wdt3t);
    cudaGetSymbolAddress((void**)&xsh,   g_xsh);
    cudaGetSymbolAddress((void**)&draw3, g_draw3);
    cudaGetSymbolAddress((void**)&yh,    g_yh);

    static bool attr_done = false;
    if (!attr_done) {
        cudaFuncSetAttribute(gemm_tc<0>, cudaFuncAttributeMaxDynamicSharedMemorySize, SMEM_TC_BYTES);
        cudaFuncSetAttribute(gemm_tc<1>, cudaFuncAttributeMaxDynamicSharedMemorySize, SMEM_TC_BYTES);
        cudaFuncSetAttribute(gemm_tc<2>, cudaFuncAttributeMaxDynamicSharedMemorySize, SMEM_TC_BYTES);
        cudaFuncSetAttribute(gemm_tc<3>, cudaFuncAttributeMaxDynamicSharedMemorySize, SMEM_TC_BYTES);
        cudaFuncSetAttribute(scan_kernel, cudaFuncAttributeMaxDynamicSharedMemorySize, SC_SMEM);
        attr_done = true;
    }

    // launches 1..3 (keeps gemm_tc<0> as 4th launch for ncu comparability)
    aneg_kernel<<<(DI*DS + 255)/256, 256>>>(A_log);
    cvt_half_kernel<<<(MROWS*DM + 255)/256, 256>>>(x, xh, MROWS*DM);
    tcvt_kernel<<<dim3(N1/32, DM/32), dim3(32, 8)>>>(Wi, Wit, DM, N1);

    // GEMM1 (4th launch): xh @ Wit^T + bi -> silu -> xs fp32 + xs fp16 | sres
    gemm_tc<0><<<dim3(N1/128, MROWS/128), 128, SMEM_TC_BYTES>>>(
        xh, Wit, bi, nullptr, xs, sres, nullptr, xsh, MROWS, N1, DM, DM);

    wdt3t_kernel<<<(DS*DI + 255)/256, 256>>>(Wdt);
    tcvt_kernel<<<dim3(N2/32, DI/32), dim3(32, 8)>>>(Wx, Wxt, DI, N2);
    tcvt_kernel<<<dim3(DM/32, DI/32), dim3(32, 8)>>>(Wo, Wot, DI, DM);

    // GEMM2: xsh @ Wxt^T + bx -> draw3(hi/hi/lo fp16) | Bsel | Csel
    gemm_tc<1><<<dim3(N2/128, MROWS/128), 128, SMEM_TC_BYTES>>>(
        xsh, Wxt, bx, nullptr, nullptr, Bsel, Csel, draw3, MROWS, N2, DI, DI);

    // GEMM3 (stacked-K fp16x2): draw3 @ Wdt3t^T + bdt -> softplus -> delta
    gemm_tc<2><<<dim3(DI/128, MROWS/128), 128, SMEM_TC_BYTES>>>(
        draw3, Wdt3t, bdt, nullptr, delta, nullptr, nullptr, nullptr, MROWS, DI, K3, K3);

    // selective scan v3 (emits fp16 y); delta dead afterwards -> reuse as z2
    scan_kernel<<<dim3(DI/32, BB), 256, SC_SMEM>>>(delta, Bsel, xs, Csel, sres, Dp, yh);

    // GEMM4 split-K=2 deterministic: slice0 -> z (+bias+residual), slice1 -> delta(z2)
    gemm_tc<3><<<dim3(DM/128, MROWS/128, 2), 128, SMEM_TC_BYTES>>>(
        yh, Wot, bo, x, z, delta, nullptr, nullptr, MROWS, DM, DI/2, DI);

    // layernorm (z + z2) -> out
    ln_kernel<<<MROWS, 256>>>(z, delta, gamma, beta, out);
}